// round 13
// baseline (speedup 1.0000x reference)
#include <cuda_runtime.h>
#include <math.h>

// Problem constants (fixed by the dataset)
#define NN 10000   // nodes
#define PP 25000   // edge-pairs
#define BB 8       // batch
#define FF 16      // feats
#define MM 32      // MLP width
#define TWO_F (2*FF)          // 32
#define NODE_STRIDE (BB*FF)   // 128 floats per node
#define XELEMS (NN*NODE_STRIDE)

// intermediate node-state buffer (layer-0 output acts), [N][B][F]
__device__ __align__(16) float g_x1[XELEMS];

// ---------------------------------------------------------------------------
// f32x2 packed-math helpers (sm_103a)
__device__ __forceinline__ unsigned long long pk2(float x, float y) {
    unsigned long long r;
    asm("mov.b64 %0,{%1,%2};" : "=l"(r) : "f"(x), "f"(y));
    return r;
}
__device__ __forceinline__ void upk2(unsigned long long v, float& x, float& y) {
    asm("mov.b64 {%0,%1},%2;" : "=f"(x), "=f"(y) : "l"(v));
}
__device__ __forceinline__ unsigned long long fma2(unsigned long long a,
                                                   unsigned long long b,
                                                   unsigned long long c) {
    unsigned long long d;
    asm("fma.rn.f32x2 %0,%1,%2,%3;" : "=l"(d) : "l"(a), "l"(b), "l"(c));
    return d;
}
__device__ __forceinline__ float silu_f(float v) {
    return __fdividef(v, 1.0f + __expf(-v));
}
// cp.async 16B copy (global -> shared), bypassing registers
__device__ __forceinline__ void cpa16(float* dst_smem, const float* src) {
    unsigned saddr = (unsigned)__cvta_generic_to_shared(dst_smem);
    asm volatile("cp.async.cg.shared.global [%0], [%1], 16;" :: "r"(saddr), "l"(src));
}
#define CP_COMMIT() asm volatile("cp.async.commit_group;")
#define CP_WAIT(n)  asm volatile("cp.async.wait_group %0;" :: "n"(n))

// ---------------------------------------------------------------------------
// profiler-alignment dummies (keep 5 launches per iteration, edges at 3,4)
__global__ void dummy_kernel() {}

// zero g_x1 and d_out (layer 0 reads h directly; no transpose needed)
__global__ void zero_kernel(float* __restrict__ out) {
    int idx = blockIdx.x * blockDim.x + threadIdx.x;
    if (idx >= XELEMS / 4) return;
    const float4 z = make_float4(0.f, 0.f, 0.f, 0.f);
    ((float4*)g_x1)[idx] = z;
    ((float4*)out)[idx]  = z;
}

// ---------------------------------------------------------------------------
// One warp per edge-pair. 2-stage cp.async weight ring, ping-pong k-major
// activations. ALL bias values are preloaded into registers at warp start
// (concurrent with the cp.async prefetch ramp) so no layer's accumulator
// init waits on a fresh DRAM load.
//   input  addr = node*SNI + b*SBI + f
//   output addr = node*SNO + b*SBO + f
#define WPB 4  // warps per block: ~41KB smem -> 5 blocks = 20 warps/SM

__device__ __forceinline__ void stage_issue(float* dst, const float* src,
                                            int lane, int nfloats) {
    #pragma unroll
    for (int i = lane * 4; i < nfloats; i += 128)
        cpa16(dst + i, src + i);
    CP_COMMIT();
}

// one MLP layer: [B,32] @ [32,32] + bias(reg) + silu; weights from smem stage
__device__ __forceinline__ void mlp32_layer_sm(const float* __restrict__ Wsm,
                                               float bv,
                                               const float (*cur)[BB],
                                               float (*nxt)[BB],
                                               int lane)
{
    unsigned long long acc2[4];
    #pragma unroll
    for (int j = 0; j < 4; j++) acc2[j] = pk2(bv, bv);
    #pragma unroll
    for (int k = 0; k < MM; k++) {
        const float w = Wsm[k * MM + lane];
        const unsigned long long w2 = pk2(w, w);
        const ulonglong2* row = (const ulonglong2*)cur[k];
        const ulonglong2 r0 = row[0];
        const ulonglong2 r1 = row[1];
        acc2[0] = fma2(r0.x, w2, acc2[0]);
        acc2[1] = fma2(r0.y, w2, acc2[1]);
        acc2[2] = fma2(r1.x, w2, acc2[2]);
        acc2[3] = fma2(r1.y, w2, acc2[3]);
    }
    float s[8];
    #pragma unroll
    for (int j = 0; j < 4; j++) {
        float a, b;
        upk2(acc2[j], a, b);
        s[2 * j]     = silu_f(a);
        s[2 * j + 1] = silu_f(b);
    }
    *(float4*)&nxt[lane][0] = make_float4(s[0], s[1], s[2], s[3]);
    *(float4*)&nxt[lane][4] = make_float4(s[4], s[5], s[6], s[7]);
}

template<int SNI, int SBI, int SNO, int SBO>
__global__ void __launch_bounds__(WPB * 32)
edge_kernel(const float* __restrict__ Wi0,  const float* __restrict__ Wih,
            const float* __restrict__ Wiout,const float* __restrict__ bi0,
            const float* __restrict__ bih,  const float* __restrict__ biout,
            const float* __restrict__ Wf0,  const float* __restrict__ Wfh,
            const float* __restrict__ Wfout,const float* __restrict__ bf0,
            const float* __restrict__ bfh,  const float* __restrict__ bfout,
            const int* __restrict__ src,    const int* __restrict__ dst,
            const float* __restrict__ xcur, float* __restrict__ ybase)
{
    // per-warp: 2-stage weight ring (4KB each) + k-major act ping-pong
    __shared__ __align__(16) float wst[WPB][2][MM * MM];
    __shared__ __align__(16) float smX[WPB][2][MM][BB];

    const int w    = threadIdx.x >> 5;
    const int lane = threadIdx.x & 31;
    const int e    = blockIdx.x * WPB + w;
    if (e > PP) return;

    const bool fx   = (e == PP);
    const int  eidx = fx ? 2 * PP : e;   // fixed edge is the last entry
    const int  d = dst[eidx];
    const int  s = src[eidx];

    const int Pp = fx ? 1 : PP;
    const int pe = fx ? 0 : e;

    const float* W0   = (fx ? Wf0   : Wi0)   + (size_t)pe * (TWO_F * MM);
    const float* b0   = (fx ? bf0   : bi0)   + (size_t)pe * MM;
    const float* Wout = (fx ? Wfout : Wiout) + (size_t)pe * (MM * FF);
    const float* bout = (fx ? bfout : biout) + (size_t)pe * FF;
    const float* WhB  = fx ? Wfh : Wih;
    const float* bhB  = fx ? bfh : bih;
    const float* Wh0  = WhB + (size_t)pe * (MM * MM);
    const float* Wh1  = WhB + ((size_t)Pp + pe) * (MM * MM);
    const float* bh0  = bhB + (size_t)pe * MM;
    const float* bh1  = bhB + ((size_t)Pp + pe) * MM;

    float* st0 = &wst[w][0][0];
    float* st1 = &wst[w][1][0];

    // prefetch layer0 + hidden0 weights immediately (groups g0, g1)
    stage_issue(st0, W0,  lane, MM * MM);
    stage_issue(st1, Wh0, lane, MM * MM);

    // ---- preload ALL biases into registers NOW (latency hidden behind the
    //      cp.async ramp + gather, instead of stalling each layer's start)
    const float bv0  = b0[lane];
    const float bvh0 = bh0[lane];
    const float bvh1 = bh1[lane];
    const float ob   = bout[lane & 15];

    // ---- gather edge input into k-major smem (overlaps with prefetch)
    {
        const float* xd = xcur + (size_t)d * SNI;
        const float* xs = xcur + (size_t)s * SNI;
        const float* xg = (lane < FF) ? xd : xs;
        const int f0 = lane & 15;
        float v[BB];
        #pragma unroll
        for (int b = 0; b < BB; b++) v[b] = xg[(size_t)b * SBI + f0];
        *(float4*)&smX[w][0][lane][0] = make_float4(v[0], v[1], v[2], v[3]);
        *(float4*)&smX[w][0][lane][4] = make_float4(v[4], v[5], v[6], v[7]);
    }
    __syncwarp();

    // ---- layer 0 (st0; hidden0 streaming into st1 behind it)
    CP_WAIT(1); __syncwarp();
    mlp32_layer_sm(st0, bv0, smX[w][0], smX[w][1], lane);
    __syncwarp();                      // all lanes done reading st0
    stage_issue(st0, Wh1, lane, MM * MM);   // g2

    // ---- hidden 0 (st1)
    CP_WAIT(1); __syncwarp();
    mlp32_layer_sm(st1, bvh0, smX[w][1], smX[w][0], lane);
    __syncwarp();                      // all lanes done reading st1
    stage_issue(st1, Wout, lane, MM * FF);  // g3 (2KB)

    // ---- hidden 1 (st0)
    CP_WAIT(1); __syncwarp();
    mlp32_layer_sm(st0, bvh1, smX[w][0], smX[w][1], lane);

    // ---- output layer: [B,32] @ [32,16] from st1
    CP_WAIT(0); __syncwarp();
    const int f  = lane & 15;
    const int bg = lane >> 4;
    unsigned long long o2[2] = { pk2(ob, ob), pk2(ob, ob) };
    const float (*A)[BB] = smX[w][1];
    #pragma unroll
    for (int k = 0; k < MM; k++) {
        const float wv = st1[k * FF + f];
        const unsigned long long w2 = pk2(wv, wv);
        const ulonglong2 r = *(const ulonglong2*)&A[k][bg * 4];
        o2[0] = fma2(r.x, w2, o2[0]);
        o2[1] = fma2(r.y, w2, o2[1]);
    }
    float o[4];
    upk2(o2[0], o[0], o[1]);
    upk2(o2[1], o[2], o[3]);

    // ---- scatter: +msg to dst, -msg to src (fixed edge: + to dst only)
    float* yd = ybase + (size_t)d * SNO;
    float* ys = ybase + (size_t)s * SNO;
    #pragma unroll
    for (int j = 0; j < 4; j++) {
        const int b = bg * 4 + j;
        atomicAdd(yd + (size_t)b * SBO + f, o[j]);
        if (!fx) atomicAdd(ys + (size_t)b * SBO + f, -o[j]);
    }
}

// ---------------------------------------------------------------------------
extern "C" void kernel_launch(void* const* d_in, const int* in_sizes, int n_in,
                              void* d_out, int out_size) {
    const float* h     = (const float*)d_in[0];
    const float* Wi0   = (const float*)d_in[1];
    const float* Wih   = (const float*)d_in[2];
    const float* Wiout = (const float*)d_in[3];
    const float* bi0   = (const float*)d_in[4];
    const float* bih   = (const float*)d_in[5];
    const float* biout = (const float*)d_in[6];
    const float* Wf0   = (const float*)d_in[7];
    const float* Wfh   = (const float*)d_in[8];
    const float* Wfout = (const float*)d_in[9];
    const float* bf0   = (const float*)d_in[10];
    const float* bfh   = (const float*)d_in[11];
    const float* bfout = (const float*)d_in[12];
    const int*   src   = (const int*)d_in[13];
    const int*   dst   = (const int*)d_in[14];
    float*       out   = (float*)d_out;

    const int tb = 256;
    const int zblocks = (XELEMS / 4 + tb - 1) / tb;
    const int eblocks = (PP + 1 + WPB - 1) / WPB;

    float* x1 = nullptr;
    cudaGetSymbolAddress((void**)&x1, g_x1);   // host-side address query only

    dummy_kernel<<<1, 32>>>();

    zero_kernel<<<zblocks, tb>>>(out);

    // layer 0: h [B][N][F] -> g_x1 [N][B][F]
    edge_kernel<FF, NN * FF, NODE_STRIDE, FF><<<eblocks, WPB * 32>>>(
        Wi0, Wih, Wiout, bi0, bih, biout,
        Wf0, Wfh, Wfout, bf0, bfh, bfout,
        src, dst, h, x1);

    // layer 1: g_x1 [N][B][F] -> d_out [B][N][F] (transpose folded in)
    edge_kernel<NODE_STRIDE, FF, FF, NN * FF><<<eblocks, WPB * 32>>>(
        Wi0   + (size_t)PP * TWO_F * MM,
        Wih   + (size_t)2 * PP * MM * MM,
        Wiout + (size_t)PP * MM * FF,
        bi0   + (size_t)PP * MM,
        bih   + (size_t)2 * PP * MM,
        biout + (size_t)PP * FF,
        Wf0   + (size_t)TWO_F * MM,
        Wfh   + (size_t)2 * MM * MM,
        Wfout + (size_t)MM * FF,
        bf0   + (size_t)MM,
        bfh   + (size_t)2 * MM,
        bfout + (size_t)FF,
        src, dst, x1, out);

    dummy_kernel<<<1, 32>>>();   // keeps 5 launches/iteration for ncu slot
}

// round 14
// speedup vs baseline: 1.0029x; 1.0029x over previous
#include <cuda_runtime.h>
#include <math.h>

// Problem constants (fixed by the dataset)
#define NN 10000   // nodes
#define PP 25000   // edge-pairs
#define BB 8       // batch
#define FF 16      // feats
#define MM 32      // MLP width
#define TWO_F (2*FF)          // 32
#define NODE_STRIDE (BB*FF)   // 128 floats per node
#define XELEMS (NN*NODE_STRIDE)

// intermediate node-state buffer (layer-0 output acts), [N][B][F]
__device__ __align__(16) float g_x1[XELEMS];

// ---------------------------------------------------------------------------
// f32x2 packed-math helpers (sm_103a)
__device__ __forceinline__ unsigned long long pk2(float x, float y) {
    unsigned long long r;
    asm("mov.b64 %0,{%1,%2};" : "=l"(r) : "f"(x), "f"(y));
    return r;
}
__device__ __forceinline__ void upk2(unsigned long long v, float& x, float& y) {
    asm("mov.b64 {%0,%1},%2;" : "=f"(x), "=f"(y) : "l"(v));
}
__device__ __forceinline__ unsigned long long fma2(unsigned long long a,
                                                   unsigned long long b,
                                                   unsigned long long c) {
    unsigned long long d;
    asm("fma.rn.f32x2 %0,%1,%2,%3;" : "=l"(d) : "l"(a), "l"(b), "l"(c));
    return d;
}
__device__ __forceinline__ float silu_f(float v) {
    return __fdividef(v, 1.0f + __expf(-v));
}
// cp.async 16B copy (global -> shared), bypassing registers
__device__ __forceinline__ void cpa16(float* dst_smem, const float* src) {
    unsigned saddr = (unsigned)__cvta_generic_to_shared(dst_smem);
    asm volatile("cp.async.cg.shared.global [%0], [%1], 16;" :: "r"(saddr), "l"(src));
}
#define CP_COMMIT() asm volatile("cp.async.commit_group;")
#define CP_WAIT(n)  asm volatile("cp.async.wait_group %0;" :: "n"(n))

// ---------------------------------------------------------------------------
// profiler-alignment dummies (keep 5 launches per iteration, edges at 3,4)
__global__ void dummy_kernel() {}

// zero g_x1 and d_out (layer 0 reads h directly; no transpose needed)
__global__ void zero_kernel(float* __restrict__ out) {
    int idx = blockIdx.x * blockDim.x + threadIdx.x;
    if (idx >= XELEMS / 4) return;
    const float4 z = make_float4(0.f, 0.f, 0.f, 0.f);
    ((float4*)g_x1)[idx] = z;
    ((float4*)out)[idx]  = z;
}

// ---------------------------------------------------------------------------
// One warp per edge-pair. 2-stage cp.async weight ring, ping-pong k-major
// activations. ALL bias values are preloaded into registers at warp start
// (concurrent with the cp.async prefetch ramp) so no layer's accumulator
// init waits on a fresh DRAM load.
//   input  addr = node*SNI + b*SBI + f
//   output addr = node*SNO + b*SBO + f
#define WPB 4  // warps per block: ~41KB smem -> 5 blocks = 20 warps/SM

__device__ __forceinline__ void stage_issue(float* dst, const float* src,
                                            int lane, int nfloats) {
    #pragma unroll
    for (int i = lane * 4; i < nfloats; i += 128)
        cpa16(dst + i, src + i);
    CP_COMMIT();
}

// one MLP layer: [B,32] @ [32,32] + bias(reg) + silu; weights from smem stage
__device__ __forceinline__ void mlp32_layer_sm(const float* __restrict__ Wsm,
                                               float bv,
                                               const float (*cur)[BB],
                                               float (*nxt)[BB],
                                               int lane)
{
    unsigned long long acc2[4];
    #pragma unroll
    for (int j = 0; j < 4; j++) acc2[j] = pk2(bv, bv);
    #pragma unroll
    for (int k = 0; k < MM; k++) {
        const float w = Wsm[k * MM + lane];
        const unsigned long long w2 = pk2(w, w);
        const ulonglong2* row = (const ulonglong2*)cur[k];
        const ulonglong2 r0 = row[0];
        const ulonglong2 r1 = row[1];
        acc2[0] = fma2(r0.x, w2, acc2[0]);
        acc2[1] = fma2(r0.y, w2, acc2[1]);
        acc2[2] = fma2(r1.x, w2, acc2[2]);
        acc2[3] = fma2(r1.y, w2, acc2[3]);
    }
    float s[8];
    #pragma unroll
    for (int j = 0; j < 4; j++) {
        float a, b;
        upk2(acc2[j], a, b);
        s[2 * j]     = silu_f(a);
        s[2 * j + 1] = silu_f(b);
    }
    *(float4*)&nxt[lane][0] = make_float4(s[0], s[1], s[2], s[3]);
    *(float4*)&nxt[lane][4] = make_float4(s[4], s[5], s[6], s[7]);
}

template<int SNI, int SBI, int SNO, int SBO>
__global__ void __launch_bounds__(WPB * 32)
edge_kernel(const float* __restrict__ Wi0,  const float* __restrict__ Wih,
            const float* __restrict__ Wiout,const float* __restrict__ bi0,
            const float* __restrict__ bih,  const float* __restrict__ biout,
            const float* __restrict__ Wf0,  const float* __restrict__ Wfh,
            const float* __restrict__ Wfout,const float* __restrict__ bf0,
            const float* __restrict__ bfh,  const float* __restrict__ bfout,
            const int* __restrict__ src,    const int* __restrict__ dst,
            const float* __restrict__ xcur, float* __restrict__ ybase)
{
    // per-warp: 2-stage weight ring (4KB each) + k-major act ping-pong
    __shared__ __align__(16) float wst[WPB][2][MM * MM];
    __shared__ __align__(16) float smX[WPB][2][MM][BB];

    const int w    = threadIdx.x >> 5;
    const int lane = threadIdx.x & 31;
    const int e    = blockIdx.x * WPB + w;
    if (e > PP) return;

    const bool fx   = (e == PP);
    const int  eidx = fx ? 2 * PP : e;   // fixed edge is the last entry
    const int  d = dst[eidx];
    const int  s = src[eidx];

    const int Pp = fx ? 1 : PP;
    const int pe = fx ? 0 : e;

    const float* W0   = (fx ? Wf0   : Wi0)   + (size_t)pe * (TWO_F * MM);
    const float* b0   = (fx ? bf0   : bi0)   + (size_t)pe * MM;
    const float* Wout = (fx ? Wfout : Wiout) + (size_t)pe * (MM * FF);
    const float* bout = (fx ? bfout : biout) + (size_t)pe * FF;
    const float* WhB  = fx ? Wfh : Wih;
    const float* bhB  = fx ? bfh : bih;
    const float* Wh0  = WhB + (size_t)pe * (MM * MM);
    const float* Wh1  = WhB + ((size_t)Pp + pe) * (MM * MM);
    const float* bh0  = bhB + (size_t)pe * MM;
    const float* bh1  = bhB + ((size_t)Pp + pe) * MM;

    float* st0 = &wst[w][0][0];
    float* st1 = &wst[w][1][0];

    // prefetch layer0 + hidden0 weights immediately (groups g0, g1)
    stage_issue(st0, W0,  lane, MM * MM);
    stage_issue(st1, Wh0, lane, MM * MM);

    // ---- preload ALL biases into registers NOW (latency hidden behind the
    //      cp.async ramp + gather, instead of stalling each layer's start)
    const float bv0  = b0[lane];
    const float bvh0 = bh0[lane];
    const float bvh1 = bh1[lane];
    const float ob   = bout[lane & 15];

    // ---- gather edge input into k-major smem (overlaps with prefetch)
    {
        const float* xd = xcur + (size_t)d * SNI;
        const float* xs = xcur + (size_t)s * SNI;
        const float* xg = (lane < FF) ? xd : xs;
        const int f0 = lane & 15;
        float v[BB];
        #pragma unroll
        for (int b = 0; b < BB; b++) v[b] = xg[(size_t)b * SBI + f0];
        *(float4*)&smX[w][0][lane][0] = make_float4(v[0], v[1], v[2], v[3]);
        *(float4*)&smX[w][0][lane][4] = make_float4(v[4], v[5], v[6], v[7]);
    }
    __syncwarp();

    // ---- layer 0 (st0; hidden0 streaming into st1 behind it)
    CP_WAIT(1); __syncwarp();
    mlp32_layer_sm(st0, bv0, smX[w][0], smX[w][1], lane);
    __syncwarp();                      // all lanes done reading st0
    stage_issue(st0, Wh1, lane, MM * MM);   // g2

    // ---- hidden 0 (st1)
    CP_WAIT(1); __syncwarp();
    mlp32_layer_sm(st1, bvh0, smX[w][1], smX[w][0], lane);
    __syncwarp();                      // all lanes done reading st1
    stage_issue(st1, Wout, lane, MM * FF);  // g3 (2KB)

    // ---- hidden 1 (st0)
    CP_WAIT(1); __syncwarp();
    mlp32_layer_sm(st0, bvh1, smX[w][0], smX[w][1], lane);

    // ---- output layer: [B,32] @ [32,16] from st1
    CP_WAIT(0); __syncwarp();
    const int f  = lane & 15;
    const int bg = lane >> 4;
    unsigned long long o2[2] = { pk2(ob, ob), pk2(ob, ob) };
    const float (*A)[BB] = smX[w][1];
    #pragma unroll
    for (int k = 0; k < MM; k++) {
        const float wv = st1[k * FF + f];
        const unsigned long long w2 = pk2(wv, wv);
        const ulonglong2 r = *(const ulonglong2*)&A[k][bg * 4];
        o2[0] = fma2(r.x, w2, o2[0]);
        o2[1] = fma2(r.y, w2, o2[1]);
    }
    float o[4];
    upk2(o2[0], o[0], o[1]);
    upk2(o2[1], o[2], o[3]);

    // ---- scatter: +msg to dst, -msg to src (fixed edge: + to dst only)
    float* yd = ybase + (size_t)d * SNO;
    float* ys = ybase + (size_t)s * SNO;
    #pragma unroll
    for (int j = 0; j < 4; j++) {
        const int b = bg * 4 + j;
        atomicAdd(yd + (size_t)b * SBO + f, o[j]);
        if (!fx) atomicAdd(ys + (size_t)b * SBO + f, -o[j]);
    }
}

// ---------------------------------------------------------------------------
extern "C" void kernel_launch(void* const* d_in, const int* in_sizes, int n_in,
                              void* d_out, int out_size) {
    const float* h     = (const float*)d_in[0];
    const float* Wi0   = (const float*)d_in[1];
    const float* Wih   = (const float*)d_in[2];
    const float* Wiout = (const float*)d_in[3];
    const float* bi0   = (const float*)d_in[4];
    const float* bih   = (const float*)d_in[5];
    const float* biout = (const float*)d_in[6];
    const float* Wf0   = (const float*)d_in[7];
    const float* Wfh   = (const float*)d_in[8];
    const float* Wfout = (const float*)d_in[9];
    const float* bf0   = (const float*)d_in[10];
    const float* bfh   = (const float*)d_in[11];
    const float* bfout = (const float*)d_in[12];
    const int*   src   = (const int*)d_in[13];
    const int*   dst   = (const int*)d_in[14];
    float*       out   = (float*)d_out;

    const int tb = 256;
    const int zblocks = (XELEMS / 4 + tb - 1) / tb;
    const int eblocks = (PP + 1 + WPB - 1) / WPB;

    float* x1 = nullptr;
    cudaGetSymbolAddress((void**)&x1, g_x1);   // host-side address query only

    dummy_kernel<<<1, 32>>>();

    zero_kernel<<<zblocks, tb>>>(out);

    // layer 0: h [B][N][F] -> g_x1 [N][B][F]
    edge_kernel<FF, NN * FF, NODE_STRIDE, FF><<<eblocks, WPB * 32>>>(
        Wi0, Wih, Wiout, bi0, bih, biout,
        Wf0, Wfh, Wfout, bf0, bfh, bfout,
        src, dst, h, x1);

    // layer 1: g_x1 [N][B][F] -> d_out [B][N][F] (transpose folded in)
    edge_kernel<NODE_STRIDE, FF, FF, NN * FF><<<eblocks, WPB * 32>>>(
        Wi0   + (size_t)PP * TWO_F * MM,
        Wih   + (size_t)2 * PP * MM * MM,
        Wiout + (size_t)PP * MM * FF,
        bi0   + (size_t)PP * MM,
        bih   + (size_t)2 * PP * MM,
        biout + (size_t)PP * FF,
        Wf0   + (size_t)TWO_F * MM,
        Wfh   + (size_t)2 * MM * MM,
        Wfout + (size_t)MM * FF,
        bf0   + (size_t)MM,
        bfh   + (size_t)2 * MM,
        bfout + (size_t)FF,
        src, dst, x1, out);

    dummy_kernel<<<1, 32>>>();   // keeps 5 launches/iteration for ncu slot
}

// round 15
// speedup vs baseline: 1.0264x; 1.0234x over previous
#include <cuda_runtime.h>
#include <math.h>

// Problem constants (fixed by the dataset)
#define NN 10000   // nodes
#define PP 25000   // edge-pairs
#define BB 8       // batch
#define FF 16      // feats
#define MM 32      // MLP width
#define TWO_F (2*FF)          // 32
#define NODE_STRIDE (BB*FF)   // 128 floats per node
#define XELEMS (NN*NODE_STRIDE)

// intermediate node-state buffer (layer-0 output acts), [N][B][F]
__device__ __align__(16) float g_x1[XELEMS];

// ---------------------------------------------------------------------------
// f32x2 packed-math helpers (sm_103a)
__device__ __forceinline__ unsigned long long pk2(float x, float y) {
    unsigned long long r;
    asm("mov.b64 %0,{%1,%2};" : "=l"(r) : "f"(x), "f"(y));
    return r;
}
__device__ __forceinline__ void upk2(unsigned long long v, float& x, float& y) {
    asm("mov.b64 {%0,%1},%2;" : "=f"(x), "=f"(y) : "l"(v));
}
__device__ __forceinline__ unsigned long long fma2(unsigned long long a,
                                                   unsigned long long b,
                                                   unsigned long long c) {
    unsigned long long d;
    asm("fma.rn.f32x2 %0,%1,%2,%3;" : "=l"(d) : "l"(a), "l"(b), "l"(c));
    return d;
}
__device__ __forceinline__ float silu_f(float v) {
    return __fdividef(v, 1.0f + __expf(-v));
}
// cp.async 16B copy (global -> shared), bypassing registers
__device__ __forceinline__ void cpa16(float* dst_smem, const float* src) {
    unsigned saddr = (unsigned)__cvta_generic_to_shared(dst_smem);
    asm volatile("cp.async.cg.shared.global [%0], [%1], 16;" :: "r"(saddr), "l"(src));
}
#define CP_COMMIT() asm volatile("cp.async.commit_group;")
#define CP_WAIT(n)  asm volatile("cp.async.wait_group %0;" :: "n"(n))

// ---------------------------------------------------------------------------
// zero g_x1 and d_out (layer 0 reads h directly; no transpose needed)
__global__ void zero_kernel(float* __restrict__ out) {
    int idx = blockIdx.x * blockDim.x + threadIdx.x;
    if (idx >= XELEMS / 4) return;
    const float4 z = make_float4(0.f, 0.f, 0.f, 0.f);
    ((float4*)g_x1)[idx] = z;
    ((float4*)out)[idx]  = z;
}

// ---------------------------------------------------------------------------
// One warp per edge-pair. 2-stage cp.async weight ring + IN-PLACE k-major
// activations (syncwarp WAR fence between the read-all FMA loop and the
// per-lane row store). 36.5KB smem + <=85 regs -> 6 blocks = 24 warps/SM,
// i.e. 24 concurrent per-warp weight streams (up from 20).
//   input  addr = node*SNI + b*SBI + f
//   output addr = node*SNO + b*SBO + f
#define WPB 4

__device__ __forceinline__ void stage_issue(float* dst, const float* src,
                                            int lane, int nfloats) {
    #pragma unroll
    for (int i = lane * 4; i < nfloats; i += 128)
        cpa16(dst + i, src + i);
    CP_COMMIT();
}

// one MLP layer: [B,32] @ [32,32] + bias(reg) + silu; in-place activations
__device__ __forceinline__ void mlp32_layer_ip(const float* __restrict__ Wsm,
                                               float bv,
                                               float (*X)[BB], int lane)
{
    unsigned long long acc2[4];
    #pragma unroll
    for (int j = 0; j < 4; j++) acc2[j] = pk2(bv, bv);
    #pragma unroll
    for (int k = 0; k < MM; k++) {
        const float w = Wsm[k * MM + lane];
        const unsigned long long w2 = pk2(w, w);
        const ulonglong2* row = (const ulonglong2*)X[k];
        const ulonglong2 r0 = row[0];
        const ulonglong2 r1 = row[1];
        acc2[0] = fma2(r0.x, w2, acc2[0]);
        acc2[1] = fma2(r0.y, w2, acc2[1]);
        acc2[2] = fma2(r1.x, w2, acc2[2]);
        acc2[3] = fma2(r1.y, w2, acc2[3]);
    }
    __syncwarp();   // all lanes finished reading X before anyone overwrites it
    float s[8];
    #pragma unroll
    for (int j = 0; j < 4; j++) {
        float a, b;
        upk2(acc2[j], a, b);
        s[2 * j]     = silu_f(a);
        s[2 * j + 1] = silu_f(b);
    }
    *(float4*)&X[lane][0] = make_float4(s[0], s[1], s[2], s[3]);
    *(float4*)&X[lane][4] = make_float4(s[4], s[5], s[6], s[7]);
    __syncwarp();
}

template<int SNI, int SBI, int SNO, int SBO>
__global__ void __launch_bounds__(WPB * 32, 6)
edge_kernel(const float* __restrict__ Wi0,  const float* __restrict__ Wih,
            const float* __restrict__ Wiout,const float* __restrict__ bi0,
            const float* __restrict__ bih,  const float* __restrict__ biout,
            const float* __restrict__ Wf0,  const float* __restrict__ Wfh,
            const float* __restrict__ Wfout,const float* __restrict__ bf0,
            const float* __restrict__ bfh,  const float* __restrict__ bfout,
            const int* __restrict__ src,    const int* __restrict__ dst,
            const float* __restrict__ xcur, float* __restrict__ ybase)
{
    // per-warp: 2-stage weight ring (4KB each) + in-place k-major acts (1KB)
    __shared__ __align__(16) float wst[WPB][2][MM * MM];
    __shared__ __align__(16) float smX[WPB][MM][BB];

    const int w    = threadIdx.x >> 5;
    const int lane = threadIdx.x & 31;
    const int e    = blockIdx.x * WPB + w;
    if (e > PP) return;

    const bool fx   = (e == PP);
    const int  eidx = fx ? 2 * PP : e;   // fixed edge is the last entry
    const int  d = dst[eidx];
    const int  s = src[eidx];

    const int Pp = fx ? 1 : PP;
    const int pe = fx ? 0 : e;

    const float* W0   = (fx ? Wf0   : Wi0)   + (size_t)pe * (TWO_F * MM);
    const float* b0   = (fx ? bf0   : bi0)   + (size_t)pe * MM;
    const float* Wout = (fx ? Wfout : Wiout) + (size_t)pe * (MM * FF);
    const float* bout = (fx ? bfout : biout) + (size_t)pe * FF;
    const float* WhB  = fx ? Wfh : Wih;
    const float* bhB  = fx ? bfh : bih;
    const float* Wh0  = WhB + (size_t)pe * (MM * MM);
    const float* Wh1  = WhB + ((size_t)Pp + pe) * (MM * MM);
    const float* bh0  = bhB + (size_t)pe * MM;
    const float* bh1  = bhB + ((size_t)Pp + pe) * MM;

    float* st0 = &wst[w][0][0];
    float* st1 = &wst[w][1][0];
    float (*X)[BB] = smX[w];

    // prefetch layer0 + hidden0 weights immediately (groups g0, g1)
    stage_issue(st0, W0,  lane, MM * MM);
    stage_issue(st1, Wh0, lane, MM * MM);

    // preload all biases (latency hidden behind the cp.async ramp + gather)
    const float bv0  = b0[lane];
    const float bvh0 = bh0[lane];
    const float bvh1 = bh1[lane];
    const float ob   = bout[lane & 15];

    // ---- gather edge input into k-major smem (overlaps with prefetch)
    {
        const float* xd = xcur + (size_t)d * SNI;
        const float* xs = xcur + (size_t)s * SNI;
        const float* xg = (lane < FF) ? xd : xs;
        const int f0 = lane & 15;
        float v[BB];
        #pragma unroll
        for (int b = 0; b < BB; b++) v[b] = xg[(size_t)b * SBI + f0];
        *(float4*)&X[lane][0] = make_float4(v[0], v[1], v[2], v[3]);
        *(float4*)&X[lane][4] = make_float4(v[4], v[5], v[6], v[7]);
    }
    __syncwarp();

    // ---- layer 0 (st0; hidden0 streaming into st1 behind it)
    CP_WAIT(1); __syncwarp();
    mlp32_layer_ip(st0, bv0, X, lane);
    stage_issue(st0, Wh1, lane, MM * MM);   // g2

    // ---- hidden 0 (st1)
    CP_WAIT(1); __syncwarp();
    mlp32_layer_ip(st1, bvh0, X, lane);
    stage_issue(st1, Wout, lane, MM * FF);  // g3 (2KB)

    // ---- hidden 1 (st0)
    CP_WAIT(1); __syncwarp();
    mlp32_layer_ip(st0, bvh1, X, lane);

    // ---- output layer: [B,32] @ [32,16] from st1
    CP_WAIT(0); __syncwarp();
    const int f  = lane & 15;
    const int bg = lane >> 4;
    unsigned long long o2[2] = { pk2(ob, ob), pk2(ob, ob) };
    #pragma unroll
    for (int k = 0; k < MM; k++) {
        const float wv = st1[k * FF + f];
        const unsigned long long w2 = pk2(wv, wv);
        const ulonglong2 r = *(const ulonglong2*)&X[k][bg * 4];
        o2[0] = fma2(r.x, w2, o2[0]);
        o2[1] = fma2(r.y, w2, o2[1]);
    }
    float o[4];
    upk2(o2[0], o[0], o[1]);
    upk2(o2[1], o[2], o[3]);

    // ---- scatter: +msg to dst, -msg to src (fixed edge: + to dst only)
    float* yd = ybase + (size_t)d * SNO;
    float* ys = ybase + (size_t)s * SNO;
    #pragma unroll
    for (int j = 0; j < 4; j++) {
        const int b = bg * 4 + j;
        atomicAdd(yd + (size_t)b * SBO + f, o[j]);
        if (!fx) atomicAdd(ys + (size_t)b * SBO + f, -o[j]);
    }
}

// ---------------------------------------------------------------------------
extern "C" void kernel_launch(void* const* d_in, const int* in_sizes, int n_in,
                              void* d_out, int out_size) {
    const float* h     = (const float*)d_in[0];
    const float* Wi0   = (const float*)d_in[1];
    const float* Wih   = (const float*)d_in[2];
    const float* Wiout = (const float*)d_in[3];
    const float* bi0   = (const float*)d_in[4];
    const float* bih   = (const float*)d_in[5];
    const float* biout = (const float*)d_in[6];
    const float* Wf0   = (const float*)d_in[7];
    const float* Wfh   = (const float*)d_in[8];
    const float* Wfout = (const float*)d_in[9];
    const float* bf0   = (const float*)d_in[10];
    const float* bfh   = (const float*)d_in[11];
    const float* bfout = (const float*)d_in[12];
    const int*   src   = (const int*)d_in[13];
    const int*   dst   = (const int*)d_in[14];
    float*       out   = (float*)d_out;

    const int tb = 256;
    const int zblocks = (XELEMS / 4 + tb - 1) / tb;
    const int eblocks = (PP + 1 + WPB - 1) / WPB;

    float* x1 = nullptr;
    cudaGetSymbolAddress((void**)&x1, g_x1);   // host-side address query only

    zero_kernel<<<zblocks, tb>>>(out);

    // layer 0: h [B][N][F] -> g_x1 [N][B][F]
    edge_kernel<FF, NN * FF, NODE_STRIDE, FF><<<eblocks, WPB * 32>>>(
        Wi0, Wih, Wiout, bi0, bih, biout,
        Wf0, Wfh, Wfout, bf0, bfh, bfout,
        src, dst, h, x1);

    // layer 1: g_x1 [N][B][F] -> d_out [B][N][F] (transpose folded in)
    edge_kernel<NODE_STRIDE, FF, FF, NN * FF><<<eblocks, WPB * 32>>>(
        Wi0   + (size_t)PP * TWO_F * MM,
        Wih   + (size_t)2 * PP * MM * MM,
        Wiout + (size_t)PP * MM * FF,
        bi0   + (size_t)PP * MM,
        bih   + (size_t)2 * PP * MM,
        biout + (size_t)PP * FF,
        Wf0   + (size_t)TWO_F * MM,
        Wfh   + (size_t)2 * MM * MM,
        Wfout + (size_t)MM * FF,
        bf0   + (size_t)MM,
        bfh   + (size_t)2 * MM,
        bfout + (size_t)FF,
        src, dst, x1, out);
}

// round 16
// speedup vs baseline: 1.0433x; 1.0165x over previous
#include <cuda_runtime.h>
#include <math.h>

// Problem constants (fixed by the dataset)
#define NN 10000   // nodes
#define PP 25000   // edge-pairs
#define BB 8       // batch
#define FF 16      // feats
#define MM 32      // MLP width
#define TWO_F (2*FF)          // 32
#define NODE_STRIDE (BB*FF)   // 128 floats per node
#define XELEMS (NN*NODE_STRIDE)

// intermediate node-state buffer (layer-0 output acts), [N][B][F]
__device__ __align__(16) float g_x1[XELEMS];

// ---------------------------------------------------------------------------
// f32x2 packed-math helpers (sm_103a)
__device__ __forceinline__ unsigned long long pk2(float x, float y) {
    unsigned long long r;
    asm("mov.b64 %0,{%1,%2};" : "=l"(r) : "f"(x), "f"(y));
    return r;
}
__device__ __forceinline__ void upk2(unsigned long long v, float& x, float& y) {
    asm("mov.b64 {%0,%1},%2;" : "=f"(x), "=f"(y) : "l"(v));
}
__device__ __forceinline__ unsigned long long fma2(unsigned long long a,
                                                   unsigned long long b,
                                                   unsigned long long c) {
    unsigned long long d;
    asm("fma.rn.f32x2 %0,%1,%2,%3;" : "=l"(d) : "l"(a), "l"(b), "l"(c));
    return d;
}
__device__ __forceinline__ float silu_f(float v) {
    return __fdividef(v, 1.0f + __expf(-v));
}
// cp.async 16B copy (global -> shared), bypassing registers
__device__ __forceinline__ void cpa16(float* dst_smem, const float* src) {
    unsigned saddr = (unsigned)__cvta_generic_to_shared(dst_smem);
    asm volatile("cp.async.cg.shared.global [%0], [%1], 16;" :: "r"(saddr), "l"(src));
}
#define CP_COMMIT() asm volatile("cp.async.commit_group;")
#define CP_WAIT(n)  asm volatile("cp.async.wait_group %0;" :: "n"(n))

// ---------------------------------------------------------------------------
// zero g_x1 and d_out (layer 0 reads h directly; no transpose needed)
__global__ void zero_kernel(float* __restrict__ out) {
    int idx = blockIdx.x * blockDim.x + threadIdx.x;
    if (idx >= XELEMS / 4) return;
    const float4 z = make_float4(0.f, 0.f, 0.f, 0.f);
    ((float4*)g_x1)[idx] = z;
    ((float4*)out)[idx]  = z;
}

// ---------------------------------------------------------------------------
// One warp per edge-pair. 2-stage cp.async weight ring + in-place k-major
// activations. MLP lane mapping: lane = (column pair 2i,2i+1) x (batch half h)
// so per k-iter the activation row is ONE LDS.128 wavefront (two 16B halves
// of the same 32B row) and the weight pair is ONE LDS.64 wavefront --
// cutting mlp LDS wavefronts by a third (L1tex was the 82% co-limiter).
#define WPB 4  // 36.5KB smem + <=85 regs -> 6 blocks = 24 warps/SM

__device__ __forceinline__ void stage_issue(float* dst, const float* src,
                                            int lane, int nfloats) {
    #pragma unroll
    for (int i = lane * 4; i < nfloats; i += 128)
        cpa16(dst + i, src + i);
    CP_COMMIT();
}

// one MLP layer: [B,32] @ [32,32] + bias(reg) + silu; in-place activations.
// lane covers columns (2i, 2i+1), batches 4h..4h+3  (i = lane&15, h = lane>>4)
__device__ __forceinline__ void mlp32_layer_ip(const float* __restrict__ Wsm,
                                               float2 bv2,
                                               float (*X)[BB], int lane)
{
    const int i = lane & 15;
    const int h = lane >> 4;
    unsigned long long acc2[4];
    acc2[0] = acc2[1] = pk2(bv2.x, bv2.x);   // col 2i:   (b4h,b4h+1),(b4h+2,b4h+3)
    acc2[2] = acc2[3] = pk2(bv2.y, bv2.y);   // col 2i+1: same batch pairs
    #pragma unroll
    for (int k = 0; k < MM; k++) {
        const float2 wp = *(const float2*)&Wsm[k * MM + 2 * i];   // 1 wavefront
        const unsigned long long w2a = pk2(wp.x, wp.x);
        const unsigned long long w2b = pk2(wp.y, wp.y);
        const ulonglong2 r = *(const ulonglong2*)&X[k][4 * h];    // 1 wavefront
        acc2[0] = fma2(r.x, w2a, acc2[0]);
        acc2[1] = fma2(r.y, w2a, acc2[1]);
        acc2[2] = fma2(r.x, w2b, acc2[2]);
        acc2[3] = fma2(r.y, w2b, acc2[3]);
    }
    __syncwarp();   // all lanes finished reading X before anyone overwrites it
    float s[8];
    #pragma unroll
    for (int j = 0; j < 4; j++) {
        float a, b;
        upk2(acc2[j], a, b);
        s[2 * j]     = silu_f(a);
        s[2 * j + 1] = silu_f(b);
    }
    *(float4*)&X[2 * i][4 * h]     = make_float4(s[0], s[1], s[2], s[3]);
    *(float4*)&X[2 * i + 1][4 * h] = make_float4(s[4], s[5], s[6], s[7]);
    __syncwarp();
}

template<int SNI, int SBI, int SNO, int SBO>
__global__ void __launch_bounds__(WPB * 32, 6)
edge_kernel(const float* __restrict__ Wi0,  const float* __restrict__ Wih,
            const float* __restrict__ Wiout,const float* __restrict__ bi0,
            const float* __restrict__ bih,  const float* __restrict__ biout,
            const float* __restrict__ Wf0,  const float* __restrict__ Wfh,
            const float* __restrict__ Wfout,const float* __restrict__ bf0,
            const float* __restrict__ bfh,  const float* __restrict__ bfout,
            const int* __restrict__ src,    const int* __restrict__ dst,
            const float* __restrict__ xcur, float* __restrict__ ybase)
{
    // per-warp: 2-stage weight ring (4KB each) + in-place k-major acts (1KB)
    __shared__ __align__(16) float wst[WPB][2][MM * MM];
    __shared__ __align__(16) float smX[WPB][MM][BB];

    const int w    = threadIdx.x >> 5;
    const int lane = threadIdx.x & 31;
    const int e    = blockIdx.x * WPB + w;
    if (e > PP) return;

    const bool fx   = (e == PP);
    const int  eidx = fx ? 2 * PP : e;   // fixed edge is the last entry
    const int  d = dst[eidx];
    const int  s = src[eidx];

    const int Pp = fx ? 1 : PP;
    const int pe = fx ? 0 : e;

    const float* W0   = (fx ? Wf0   : Wi0)   + (size_t)pe * (TWO_F * MM);
    const float* b0   = (fx ? bf0   : bi0)   + (size_t)pe * MM;
    const float* Wout = (fx ? Wfout : Wiout) + (size_t)pe * (MM * FF);
    const float* bout = (fx ? bfout : biout) + (size_t)pe * FF;
    const float* WhB  = fx ? Wfh : Wih;
    const float* bhB  = fx ? bfh : bih;
    const float* Wh0  = WhB + (size_t)pe * (MM * MM);
    const float* Wh1  = WhB + ((size_t)Pp + pe) * (MM * MM);
    const float* bh0  = bhB + (size_t)pe * MM;
    const float* bh1  = bhB + ((size_t)Pp + pe) * MM;

    float* st0 = &wst[w][0][0];
    float* st1 = &wst[w][1][0];
    float (*X)[BB] = smX[w];

    // prefetch layer0 + hidden0 weights immediately (groups g0, g1)
    stage_issue(st0, W0,  lane, MM * MM);
    stage_issue(st1, Wh0, lane, MM * MM);

    // preload all biases as column pairs (latency hidden behind the ramp)
    const int ip = lane & 15;
    const float2 bv0  = *(const float2*)&b0[2 * ip];
    const float2 bvh0 = *(const float2*)&bh0[2 * ip];
    const float2 bvh1 = *(const float2*)&bh1[2 * ip];
    const float  ob   = bout[ip];

    // ---- gather edge input into k-major smem (overlaps with prefetch)
    {
        const float* xd = xcur + (size_t)d * SNI;
        const float* xs = xcur + (size_t)s * SNI;
        const float* xg = (lane < FF) ? xd : xs;
        const int f0 = lane & 15;
        float v[BB];
        #pragma unroll
        for (int b = 0; b < BB; b++) v[b] = xg[(size_t)b * SBI + f0];
        *(float4*)&X[lane][0] = make_float4(v[0], v[1], v[2], v[3]);
        *(float4*)&X[lane][4] = make_float4(v[4], v[5], v[6], v[7]);
    }
    __syncwarp();

    // ---- layer 0 (st0; hidden0 streaming into st1 behind it)
    CP_WAIT(1); __syncwarp();
    mlp32_layer_ip(st0, bv0, X, lane);
    stage_issue(st0, Wh1, lane, MM * MM);   // g2

    // ---- hidden 0 (st1)
    CP_WAIT(1); __syncwarp();
    mlp32_layer_ip(st1, bvh0, X, lane);
    stage_issue(st1, Wout, lane, MM * FF);  // g3 (2KB)

    // ---- hidden 1 (st0)
    CP_WAIT(1); __syncwarp();
    mlp32_layer_ip(st0, bvh1, X, lane);

    // ---- output layer: [B,32] @ [32,16] from st1
    CP_WAIT(0); __syncwarp();
    const int f  = ip;
    const int bg = lane >> 4;
    unsigned long long o2[2] = { pk2(ob, ob), pk2(ob, ob) };
    #pragma unroll
    for (int k = 0; k < MM; k++) {
        const float wv = st1[k * FF + f];
        const unsigned long long w2 = pk2(wv, wv);
        const ulonglong2 r = *(const ulonglong2*)&X[k][bg * 4];
        o2[0] = fma2(r.x, w2, o2[0]);
        o2[1] = fma2(r.y, w2, o2[1]);
    }
    float o[4];
    upk2(o2[0], o[0], o[1]);
    upk2(o2[1], o[2], o[3]);

    // ---- scatter: +msg to dst, -msg to src (fixed edge: + to dst only)
    float* yd = ybase + (size_t)d * SNO;
    float* ys = ybase + (size_t)s * SNO;
    #pragma unroll
    for (int j = 0; j < 4; j++) {
        const int b = bg * 4 + j;
        atomicAdd(yd + (size_t)b * SBO + f, o[j]);
        if (!fx) atomicAdd(ys + (size_t)b * SBO + f, -o[j]);
    }
}

// ---------------------------------------------------------------------------
extern "C" void kernel_launch(void* const* d_in, const int* in_sizes, int n_in,
                              void* d_out, int out_size) {
    const float* h     = (const float*)d_in[0];
    const float* Wi0   = (const float*)d_in[1];
    const float* Wih   = (const float*)d_in[2];
    const float* Wiout = (const float*)d_in[3];
    const float* bi0   = (const float*)d_in[4];
    const float* bih   = (const float*)d_in[5];
    const float* biout = (const float*)d_in[6];
    const float* Wf0   = (const float*)d_in[7];
    const float* Wfh   = (const float*)d_in[8];
    const float* Wfout = (const float*)d_in[9];
    const float* bf0   = (const float*)d_in[10];
    const float* bfh   = (const float*)d_in[11];
    const float* bfout = (const float*)d_in[12];
    const int*   src   = (const int*)d_in[13];
    const int*   dst   = (const int*)d_in[14];
    float*       out   = (float*)d_out;

    const int tb = 256;
    const int zblocks = (XELEMS / 4 + tb - 1) / tb;
    const int eblocks = (PP + 1 + WPB - 1) / WPB;

    float* x1 = nullptr;
    cudaGetSymbolAddress((void**)&x1, g_x1);   // host-side address query only

    zero_kernel<<<zblocks, tb>>>(out);

    // layer 0: h [B][N][F] -> g_x1 [N][B][F]
    edge_kernel<FF, NN * FF, NODE_STRIDE, FF><<<eblocks, WPB * 32>>>(
        Wi0, Wih, Wiout, bi0, bih, biout,
        Wf0, Wfh, Wfout, bf0, bfh, bfout,
        src, dst, h, x1);

    // layer 1: g_x1 [N][B][F] -> d_out [B][N][F] (transpose folded in)
    edge_kernel<NODE_STRIDE, FF, FF, NN * FF><<<eblocks, WPB * 32>>>(
        Wi0   + (size_t)PP * TWO_F * MM,
        Wih   + (size_t)2 * PP * MM * MM,
        Wiout + (size_t)PP * MM * FF,
        bi0   + (size_t)PP * MM,
        bih   + (size_t)2 * PP * MM,
        biout + (size_t)PP * FF,
        Wf0   + (size_t)TWO_F * MM,
        Wfh   + (size_t)2 * MM * MM,
        Wfout + (size_t)MM * FF,
        bf0   + (size_t)MM,
        bfh   + (size_t)2 * MM,
        bfout + (size_t)FF,
        src, dst, x1, out);
}